// round 12
// baseline (speedup 1.0000x reference)
#include <cuda_runtime.h>
#include <cuda_fp16.h>
#include <cstdint>

// Circulant GEMM on mma.sync fp16: per (channel, 2 batches) tile,
// D[56,112] = (Ah+Am)[56,56] @ Bh[56,112], fp16 2-term split.
// Each block processes 4 tiles of one channel with two fp16 smem buffers:
// tile t+1's LDG->cvt->STS stream is interleaved into tile t's mma loop,
// so only tile 0's load is exposed. A circulant fragments built once.

#define CCH 384
#define HW 56
#define PLANE 3136
#define NT 128
#define TPB 4
#define ROWB 240                      // 60 words/row, 60%32==28 -> conflict-free
#define BUF (56 * ROWB)               // 13440 per fp16 buffer
#define W_OFF (2 * BUF)               // 26880
#define SMEM_TOTAL (W_OFF + 256)      // 27136

__device__ __forceinline__ uint32_t smem_u32(const void* p) {
    uint32_t a;
    asm("{ .reg .u64 t; cvta.to.shared.u64 t, %1; cvt.u32.u64 %0, t; }" : "=r"(a) : "l"(p));
    return a;
}
__device__ __forceinline__ void ldmat4t(uint32_t r[4], uint32_t addr) {
    asm volatile("ldmatrix.sync.aligned.m8n8.x4.trans.shared.b16 {%0,%1,%2,%3}, [%4];"
                 : "=r"(r[0]), "=r"(r[1]), "=r"(r[2]), "=r"(r[3]) : "r"(addr));
}
__device__ __forceinline__ void ldmat2t(uint32_t r[2], uint32_t addr) {
    asm volatile("ldmatrix.sync.aligned.m8n8.x2.trans.shared.b16 {%0,%1}, [%2];"
                 : "=r"(r[0]), "=r"(r[1]) : "r"(addr));
}
__device__ __forceinline__ void mma16(float c[4], const uint32_t a[4],
                                      uint32_t b0, uint32_t b1) {
    asm volatile(
        "mma.sync.aligned.m16n8k16.row.col.f32.f16.f16.f32 "
        "{%0,%1,%2,%3}, {%4,%5,%6,%7}, {%8,%9}, {%0,%1,%2,%3};"
        : "+f"(c[0]), "+f"(c[1]), "+f"(c[2]), "+f"(c[3])
        : "r"(a[0]), "r"(a[1]), "r"(a[2]), "r"(a[3]), "r"(b0), "r"(b1));
}
__device__ __forceinline__ void mma8(float c[4], const uint32_t a[2], uint32_t b0) {
    asm volatile(
        "mma.sync.aligned.m16n8k8.row.col.f32.f16.f16.f32 "
        "{%0,%1,%2,%3}, {%4,%5}, {%6}, {%0,%1,%2,%3};"
        : "+f"(c[0]), "+f"(c[1]), "+f"(c[2]), "+f"(c[3])
        : "r"(a[0]), "r"(a[1]), "r"(b0));
}
__device__ __forceinline__ uint32_t bits2h(__half2 v) { return *(uint32_t*)&v; }

__device__ __forceinline__ void cvt_sts(float4 v, char* p) {
    uint2 pk;
    pk.x = bits2h(__floats2half2_rn(v.x, v.y));
    pk.y = bits2h(__floats2half2_rn(v.z, v.w));
    *(uint2*)p = pk;
}

extern __shared__ char smem[];

__global__ __launch_bounds__(NT, 6)
void gcc_conv_hmma8(const float* __restrict__ x, const float* __restrict__ weight,
                    const float* __restrict__ bias, float* __restrict__ out) {
    const int tid = threadIdx.x;
    const int c  = blockIdx.x >> 2;
    const int bq = blockIdx.x & 3;          // batch quad: batches [8bq, 8bq+8)

    float* wtab = (float*)(smem + W_OFF);
    if (tid < HW) wtab[tid] = weight[c * HW + tid];
    __syncthreads();

    const int wm = tid >> 5, lane = tid & 31;
    const int g = lane >> 2, i4 = lane & 3;
    const int r0 = wm * 16 + g;          // < 56
    const int r1 = r0 + 8;               // >= 56 only when wm==3

    // ---- A circulant fragments (hi/mid fp16): 3 k16 tiles + k8 tail ----
    uint32_t Ah[3][4], Am[3][4], Th[2], Tm[2];
#pragma unroll
    for (int kt = 0; kt < 3; kt++) {
#pragma unroll
        for (int reg = 0; reg < 4; reg++) {
            const int row = (reg & 1) ? r1 : r0;
            const int kk = kt * 16 + 2 * i4 + ((reg & 2) ? 8 : 0);
            float v0 = 0.f, v1 = 0.f;
            if (row < HW) {
                int j0 = kk - row; if (j0 < 0) j0 += HW;
                int j1 = j0 + 1;   if (j1 == HW) j1 = 0;
                v0 = wtab[j0]; v1 = wtab[j1];
            }
            __half h0 = __float2half_rn(v0), h1 = __float2half_rn(v1);
            __half m0 = __float2half_rn(v0 - __half2float(h0));
            __half m1 = __float2half_rn(v1 - __half2float(h1));
            Ah[kt][reg] = bits2h(__halves2half2(h0, h1));
            Am[kt][reg] = bits2h(__halves2half2(m0, m1));
        }
    }
#pragma unroll
    for (int reg = 0; reg < 2; reg++) {
        const int row = reg ? r1 : r0;
        const int kk = 48 + 2 * i4;
        float v0 = 0.f, v1 = 0.f;
        if (row < HW) {
            int j0 = kk - row; if (j0 < 0) j0 += HW;
            int j1 = j0 + 1;   if (j1 == HW) j1 = 0;
            v0 = wtab[j0]; v1 = wtab[j1];
        }
        __half h0 = __float2half_rn(v0), h1 = __float2half_rn(v1);
        __half m0 = __float2half_rn(v0 - __half2float(h0));
        __half m1 = __float2half_rn(v1 - __half2float(h1));
        Th[reg] = bits2h(__halves2half2(h0, h1));
        Tm[reg] = bits2h(__halves2half2(m0, m1));
    }

    // ---- full convert of tile 0 into buf0 ----
    {
        const float* xc = x + ((size_t)(bq * 8) * CCH + c) * PLANE;
#pragma unroll
        for (int b = 0; b < 2; b++) {
            const float* xb = xc + (size_t)b * CCH * PLANE;
            char* sb = smem + b * 112;
#pragma unroll
            for (int i = 0; i < 6; i++) {
                const int u = tid + NT * i;
                const int k = u / 14, wq = u - k * 14;
                cvt_sts(*(const float4*)(xb + k * HW + wq * 4),
                        sb + k * ROWB + wq * 8);
            }
            if (tid < 16) {
                const int u = 768 + tid;
                const int k = u / 14, wq = u - k * 14;
                cvt_sts(*(const float4*)(xb + k * HW + wq * 4),
                        sb + k * ROWB + wq * 8);
            }
        }
    }
    __syncthreads();

    const uint32_t sbase = smem_u32(smem);
    const int krow = (lane & 7) + ((lane >> 3) & 1) * 8;
    const int nsel = lane >> 4;
    const int tnsel = (lane >> 3) & 1;
    const float bv = bias[c];

#pragma unroll
    for (int t = 0; t < TPB; t++) {
        const int b0 = bq * 8 + 2 * t;
        const uint32_t cbuf = sbase + (uint32_t)((t & 1) * BUF);
        const uint32_t lbase = cbuf + krow * ROWB;
        const uint32_t tbase = cbuf + (48 + (lane & 7)) * ROWB;
        const bool more = (t + 1 < TPB);
        const float* xn = more
            ? x + ((size_t)(b0 + 2) * CCH + c) * PLANE : (const float*)0;
        char* nbuf = smem + ((t + 1) & 1) * BUF;

        uint32_t bh[2][4];
#pragma unroll
        for (int np = 0; np < 7; np++) {
            const int nt0 = np * 2;
            const uint32_t laddr = lbase + (uint32_t)(nt0 + nsel) * 16;
            const uint32_t taddr = tbase + (uint32_t)(nt0 + tnsel) * 16;
            if (np == 0)
                ldmat4t(bh[0], laddr);

            // issue next-tile LDGs (2 float4 groups) early
            float4 pre0, pre1;
            char *s0 = 0, *s1 = 0;
            bool v0 = false, v1 = false;
            if (more) {
                const int u0 = np * 256 + tid;
                const int u1 = u0 + 128;
                v0 = u0 < 1568;
                v1 = u1 < 1568;
                if (v0) {
                    const int b = u0 >> 9 >= 1 ? (u0 >= 784) : (u0 >= 784); // u0/784
                    const int bb = u0 >= 784;
                    const int r = u0 - 784 * bb;
                    const int k = r / 14, wq = r - k * 14;
                    pre0 = *(const float4*)(xn + (size_t)bb * CCH * PLANE + k * HW + wq * 4);
                    s0 = nbuf + bb * 112 + k * ROWB + wq * 8;
                    (void)b;
                }
                if (v1) {
                    const int bb = u1 >= 784;
                    const int r = u1 - 784 * bb;
                    const int k = r / 14, wq = r - k * 14;
                    pre1 = *(const float4*)(xn + (size_t)bb * CCH * PLANE + k * HW + wq * 4);
                    s1 = nbuf + bb * 112 + k * ROWB + wq * 8;
                }
            }

            float acc0[4] = {bv, bv, bv, bv};
            float acc1[4] = {bv, bv, bv, bv};
            uint32_t thr[2];
#pragma unroll
            for (int kt = 0; kt < 3; kt++) {
                const int cur = kt & 1, nxt = cur ^ 1;
                if (kt < 2)
                    ldmat4t(bh[nxt], laddr + (kt + 1) * 16 * ROWB);
                else
                    ldmat2t(thr, taddr);
                mma16(acc0, Ah[kt], bh[cur][0], bh[cur][1]);
                mma16(acc1, Ah[kt], bh[cur][2], bh[cur][3]);
                mma16(acc0, Am[kt], bh[cur][0], bh[cur][1]);
                mma16(acc1, Am[kt], bh[cur][2], bh[cur][3]);
            }
            if (np < 6) {
                const uint32_t laddr2 = lbase + (uint32_t)(nt0 + 2 + nsel) * 16;
                ldmat4t(bh[0], laddr2);
            }
            mma8(acc0, Th, thr[0]);
            mma8(acc1, Th, thr[1]);
            mma8(acc0, Tm, thr[0]);
            mma8(acc1, Tm, thr[1]);

            // consume the prefetched next-tile data (LDG latency covered by mmas)
            if (v0) cvt_sts(pre0, s0);
            if (v1) cvt_sts(pre1, s1);

#pragma unroll
            for (int s = 0; s < 2; s++) {
                const float* acc = s ? acc1 : acc0;
                const int n = (nt0 + s) * 8 + 2 * i4;
                const int b = (n >= HW);
                const int wcol = n - b * HW;
                float* op = out + ((size_t)(b0 + b) * CCH + c) * PLANE + wcol;
                *(float2*)(op + r0 * HW) = make_float2(acc[0], acc[1]);
                if (wm != 3)
                    *(float2*)(op + r1 * HW) = make_float2(acc[2], acc[3]);
            }
        }
        __syncthreads();
    }
}

extern "C" void kernel_launch(void* const* d_in, const int* in_sizes, int n_in,
                              void* d_out, int out_size) {
    const float* x      = (const float*)d_in[0];
    const float* weight = (const float*)d_in[1];
    const float* bias   = (const float*)d_in[2];
    cudaFuncSetAttribute(gcc_conv_hmma8,
                         cudaFuncAttributeMaxDynamicSharedMemorySize, SMEM_TOTAL);
    gcc_conv_hmma8<<<CCH * 4, NT, SMEM_TOTAL>>>(x, weight, bias, (float*)d_out);
}

// round 13
// speedup vs baseline: 1.2879x; 1.2879x over previous
#include <cuda_runtime.h>
#include <cuda_fp16.h>
#include <cstdint>

// Circulant GEMM on mma.sync fp16: D[56,112] = A_c[56,56] @ X[56,112]
// per (channel, 2 batches). Single-term fp16: Ah @ Bh with fp32 accumulate.
// Error: (w-wh)*x + w*(x-xh) ~ sqrt2 * 2^-12/product -> rel_err ~4e-5 << 1e-3.
// K = 3 x k16 + k8 tail. B in natural [k][n] smem, ldmatrix.trans fetch,
// kt-level register double-buffer. 128-thread blocks, 6 blocks/SM.

#define CCH 384
#define HW 56
#define PLANE 3136
#define NT 128
#define ROWB 240                      // 60 words/row, 60%32==28 -> conflict-free
#define W_OFF (56 * ROWB)             // 13440
#define SMEM_TOTAL (W_OFF + 256)      // 13696

__device__ __forceinline__ uint32_t smem_u32(const void* p) {
    uint32_t a;
    asm("{ .reg .u64 t; cvta.to.shared.u64 t, %1; cvt.u32.u64 %0, t; }" : "=r"(a) : "l"(p));
    return a;
}
__device__ __forceinline__ void ldmat4t(uint32_t r[4], uint32_t addr) {
    asm volatile("ldmatrix.sync.aligned.m8n8.x4.trans.shared.b16 {%0,%1,%2,%3}, [%4];"
                 : "=r"(r[0]), "=r"(r[1]), "=r"(r[2]), "=r"(r[3]) : "r"(addr));
}
__device__ __forceinline__ void ldmat2t(uint32_t r[2], uint32_t addr) {
    asm volatile("ldmatrix.sync.aligned.m8n8.x2.trans.shared.b16 {%0,%1}, [%2];"
                 : "=r"(r[0]), "=r"(r[1]) : "r"(addr));
}
__device__ __forceinline__ void mma16(float c[4], const uint32_t a[4],
                                      uint32_t b0, uint32_t b1) {
    asm volatile(
        "mma.sync.aligned.m16n8k16.row.col.f32.f16.f16.f32 "
        "{%0,%1,%2,%3}, {%4,%5,%6,%7}, {%8,%9}, {%0,%1,%2,%3};"
        : "+f"(c[0]), "+f"(c[1]), "+f"(c[2]), "+f"(c[3])
        : "r"(a[0]), "r"(a[1]), "r"(a[2]), "r"(a[3]), "r"(b0), "r"(b1));
}
__device__ __forceinline__ void mma8(float c[4], const uint32_t a[2], uint32_t b0) {
    asm volatile(
        "mma.sync.aligned.m16n8k8.row.col.f32.f16.f16.f32 "
        "{%0,%1,%2,%3}, {%4,%5}, {%6}, {%0,%1,%2,%3};"
        : "+f"(c[0]), "+f"(c[1]), "+f"(c[2]), "+f"(c[3])
        : "r"(a[0]), "r"(a[1]), "r"(b0));
}
__device__ __forceinline__ uint32_t bits2h(__half2 v) { return *(uint32_t*)&v; }

extern __shared__ char smem[];

__global__ __launch_bounds__(NT, 6)
void gcc_conv_hmma9(const float* __restrict__ x, const float* __restrict__ weight,
                    const float* __restrict__ bias, float* __restrict__ out) {
    const int tid = threadIdx.x;
    const int c  = blockIdx.x >> 4;
    const int b0 = (blockIdx.x & 15) * 2;

    float* wtab = (float*)(smem + W_OFF);
    if (tid < HW) wtab[tid] = weight[c * HW + tid];
    __syncthreads();

    const int wm = tid >> 5, lane = tid & 31;
    const int g = lane >> 2, i4 = lane & 3;
    const int r0 = wm * 16 + g;          // < 56
    const int r1 = r0 + 8;               // >= 56 only when wm==3

    // ---- A circulant fragments (fp16): 3 k16 tiles + k8 tail ----
    uint32_t Ah[3][4], Th[2];
#pragma unroll
    for (int kt = 0; kt < 3; kt++) {
#pragma unroll
        for (int reg = 0; reg < 4; reg++) {
            const int row = (reg & 1) ? r1 : r0;
            const int kk = kt * 16 + 2 * i4 + ((reg & 2) ? 8 : 0);
            float v0 = 0.f, v1 = 0.f;
            if (row < HW) {
                int j0 = kk - row; if (j0 < 0) j0 += HW;
                int j1 = j0 + 1;   if (j1 == HW) j1 = 0;
                v0 = wtab[j0]; v1 = wtab[j1];
            }
            Ah[kt][reg] = bits2h(__floats2half2_rn(v0, v1));
        }
    }
#pragma unroll
    for (int reg = 0; reg < 2; reg++) {
        const int row = reg ? r1 : r0;
        const int kk = 48 + 2 * i4;
        float v0 = 0.f, v1 = 0.f;
        if (row < HW) {
            int j0 = kk - row; if (j0 < 0) j0 += HW;
            int j1 = j0 + 1;   if (j1 == HW) j1 = 0;
            v0 = wtab[j0]; v1 = wtab[j1];
        }
        Th[reg] = bits2h(__floats2half2_rn(v0, v1));
    }

    // ---- convert pass: X (2 batches) -> natural [k][n] fp16 smem ----
    const float* xc = x + ((size_t)b0 * CCH + c) * PLANE;
#pragma unroll
    for (int b = 0; b < 2; b++) {
        const float* xb = xc + (size_t)b * CCH * PLANE;
        char* sb = smem + b * 112;
#pragma unroll
        for (int i = 0; i < 7; i++) {
            const int u = tid + NT * i;
            if (u >= 784) break;
            const int k = u / 14, wq = u - k * 14;
            const float4 v = *(const float4*)(xb + k * HW + wq * 4);
            uint2 pk;
            pk.x = bits2h(__floats2half2_rn(v.x, v.y));
            pk.y = bits2h(__floats2half2_rn(v.z, v.w));
            *(uint2*)(sb + k * ROWB + wq * 8) = pk;
        }
    }
    __syncthreads();

    // ---- MMA: warp wm covers all 14 n-tiles (7 pairs); kt register pipeline ----
    const float bv = bias[c];
    const uint32_t sbase = smem_u32(smem);
    const int krow = (lane & 7) + ((lane >> 3) & 1) * 8;
    const int nsel = lane >> 4;
    const int tnsel = (lane >> 3) & 1;
    const uint32_t lbase = sbase + krow * ROWB;
    const uint32_t tbase = sbase + (48 + (lane & 7)) * ROWB;

    uint32_t bh[2][4];

#pragma unroll
    for (int np = 0; np < 7; np++) {
        const int nt0 = np * 2;
        const uint32_t laddr = lbase + (uint32_t)(nt0 + nsel) * 16;
        const uint32_t taddr = tbase + (uint32_t)(nt0 + tnsel) * 16;
        if (np == 0)                          // prime the pipeline
            ldmat4t(bh[0], laddr);
        float acc0[4] = {bv, bv, bv, bv};
        float acc1[4] = {bv, bv, bv, bv};
        uint32_t thr[2];
#pragma unroll
        for (int kt = 0; kt < 3; kt++) {
            const int cur = kt & 1, nxt = cur ^ 1;
            if (kt < 2)                       // prefetch next k16 tile
                ldmat4t(bh[nxt], laddr + (kt + 1) * 16 * ROWB);
            else                              // prefetch k8 tail
                ldmat2t(thr, taddr);
            mma16(acc0, Ah[kt], bh[cur][0], bh[cur][1]);
            mma16(acc1, Ah[kt], bh[cur][2], bh[cur][3]);
        }
        if (np < 6) {                         // prefetch next pair's kt0
            const uint32_t laddr2 = lbase + (uint32_t)(nt0 + 2 + nsel) * 16;
            ldmat4t(bh[0], laddr2);
        }
        mma8(acc0, Th, thr[0]);
        mma8(acc1, Th, thr[1]);
#pragma unroll
        for (int s = 0; s < 2; s++) {
            const float* acc = s ? acc1 : acc0;
            const int n = (nt0 + s) * 8 + 2 * i4;
            const int b = (n >= HW);
            const int wcol = n - b * HW;
            float* op = out + ((size_t)(b0 + b) * CCH + c) * PLANE + wcol;
            *(float2*)(op + r0 * HW) = make_float2(acc[0], acc[1]);
            if (wm != 3)
                *(float2*)(op + r1 * HW) = make_float2(acc[2], acc[3]);
        }
    }
}

extern "C" void kernel_launch(void* const* d_in, const int* in_sizes, int n_in,
                              void* d_out, int out_size) {
    const float* x      = (const float*)d_in[0];
    const float* weight = (const float*)d_in[1];
    const float* bias   = (const float*)d_in[2];
    cudaFuncSetAttribute(gcc_conv_hmma9,
                         cudaFuncAttributeMaxDynamicSharedMemorySize, SMEM_TOTAL);
    gcc_conv_hmma9<<<CCH * 16, NT, SMEM_TOTAL>>>(x, weight, bias, (float*)d_out);
}